// round 6
// baseline (speedup 1.0000x reference)
#include <cuda_runtime.h>

typedef unsigned long long u64;
typedef unsigned int u32;

#define CAP 2097152
#define EPSBN 1e-5f
#define SGRID 1184

__device__ float4 g_h2[4 * CAP];                    // h2 plane-major: [plane p][row]
__device__ float g_stats[5][32];                    // [stage][sum 0..15 | sumsq 0..15]
__device__ __align__(16) float g_ctab[8 * 64];      // emb@wc_tail^T + bc

// ---------------- packed f32x2 helpers ----------------
__device__ __forceinline__ u64 pack2(float x, float y) {
  u64 d;
  asm("mov.b64 %0, {%1, %2};" : "=l"(d) : "r"(__float_as_uint(x)), "r"(__float_as_uint(y)));
  return d;
}
__device__ __forceinline__ void unpack2(u64 a, float& x, float& y) {
  u32 lo, hi;
  asm("mov.b64 {%0, %1}, %2;" : "=r"(lo), "=r"(hi) : "l"(a));
  x = __uint_as_float(lo); y = __uint_as_float(hi);
}
__device__ __forceinline__ u64 fma2(u64 a, u64 b, u64 c) {
  u64 d;
  asm("fma.rn.f32x2 %0, %1, %2, %3;" : "=l"(d) : "l"(a), "l"(b), "l"(c));
  return d;
}
__device__ __forceinline__ u64 ldu64(const float2* p) {
  return *reinterpret_cast<const u64*>(p);
}

// ---------------- BN folding into next linear ----------------
// y = W(x*sc + sh) + b  =>  W'[.,j] = W[.,j]*sc_j ; b' = b + W*sh
// wsp layout: wsp[j*8 + p] = (W'[2p][j], W'[2p+1][j])   (8 output pairs)
__device__ void fold_bn_layer16(int stage, float invN,
                                const float* bng, const float* bnb,
                                const float* w, const float* bias,
                                float* ss, float2* wsp, float2* fbp) {
  int t = threadIdx.x;
  if (t < 16) {
    float m = g_stats[stage][t] * invN;
    float var = fmaf(-m, m, g_stats[stage][16 + t] * invN);
    float scale = rsqrtf(var + EPSBN) * bng[t];
    ss[t] = scale;
    ss[16 + t] = bnb[t] - m * scale;
  }
  __syncthreads();
  if (t < 128) {
    int j = t >> 3, p = t & 7;
    float s = ss[j];
    wsp[j * 8 + p] = make_float2(w[(2 * p) * 16 + j] * s, w[(2 * p + 1) * 16 + j] * s);
  }
  if (t < 8) {
    float a0 = bias[2 * t], a1 = bias[2 * t + 1];
#pragma unroll
    for (int j = 0; j < 16; j++) {
      float shj = ss[16 + j];
      a0 = fmaf(w[(2 * t) * 16 + j], shj, a0);
      a1 = fmaf(w[(2 * t + 1) * 16 + j], shj, a1);
    }
    fbp[t] = make_float2(a0, a1);
  }
}

__device__ void fold_bn_layer1(float invN,
                               const float* bng, const float* bnb,
                               const float* w1, const float* b1,
                               float* ss, float2* w1p, float2* fb1p) {
  int t = threadIdx.x;
  if (t < 2) {
    float m = g_stats[0][t] * invN;
    float var = fmaf(-m, m, g_stats[0][16 + t] * invN);
    float scale = rsqrtf(var + EPSBN) * bng[t];
    ss[t] = scale;
    ss[2 + t] = bnb[t] - m * scale;
  }
  __syncthreads();
  if (t < 16) {
    int j = t >> 3, p = t & 7;
    float s = ss[j];
    w1p[j * 8 + p] = make_float2(w1[(2 * p) * 2 + j] * s, w1[(2 * p + 1) * 2 + j] * s);
  }
  if (t < 8) {
    float a0 = fmaf(w1[(2 * t) * 2 + 0], ss[2], fmaf(w1[(2 * t) * 2 + 1], ss[3], b1[2 * t]));
    float a1 = fmaf(w1[(2 * t + 1) * 2 + 0], ss[2], fmaf(w1[(2 * t + 1) * 2 + 1], ss[3], b1[2 * t + 1]));
    fb1p[t] = make_float2(a0, a1);
  }
}

// ---------------- per-row layers ----------------
__device__ __forceinline__ void compute_h1(const float2* w1p, const float2* fb1p,
                                           float x0, float x1, float h[16]) {
  u64 v0 = pack2(x0, x0), v1 = pack2(x1, x1);
#pragma unroll
  for (int p = 0; p < 8; p++) {
    u64 a = ldu64(&fb1p[p]);
    a = fma2(ldu64(&w1p[p]), v0, a);
    a = fma2(ldu64(&w1p[8 + p]), v1, a);
    float lo, hi; unpack2(a, lo, hi);
    h[2 * p] = fmaxf(lo, 0.f);
    h[2 * p + 1] = fmaxf(hi, 0.f);
  }
}

// out = relu(W' v + b'), R rows per thread (weights LDS amortized over R rows)
template <int R>
__device__ __forceinline__ void layer16(const float2* wsp, const float2* fbp,
                                        const float v[][16], float out[][16]) {
  u64 acc[R][8];
#pragma unroll
  for (int p = 0; p < 8; p++) {
    u64 b = ldu64(&fbp[p]);
#pragma unroll
    for (int r = 0; r < R; r++) acc[r][p] = b;
  }
#pragma unroll
  for (int j = 0; j < 16; j++) {
    u64 w[8];
#pragma unroll
    for (int p = 0; p < 8; p++) w[p] = ldu64(&wsp[j * 8 + p]);
#pragma unroll
    for (int r = 0; r < R; r++) {
      u64 vr = pack2(v[r][j], v[r][j]);
#pragma unroll
      for (int p = 0; p < 8; p++) acc[r][p] = fma2(w[p], vr, acc[r][p]);
    }
  }
#pragma unroll
  for (int r = 0; r < R; r++)
#pragma unroll
    for (int p = 0; p < 8; p++) {
      float a, b; unpack2(acc[r][p], a, b);
      out[r][2 * p] = fmaxf(a, 0.f);
      out[r][2 * p + 1] = fmaxf(b, 0.f);
    }
}

__device__ __forceinline__ void load_h2(int row, float h[16]) {
#pragma unroll
  for (int p = 0; p < 4; p++) {
    float4 f = g_h2[p * CAP + row];
    h[4 * p] = f.x; h[4 * p + 1] = f.y; h[4 * p + 2] = f.z; h[4 * p + 3] = f.w;
  }
}

// block-staged stats accumulation (sAcc: 32 shared floats, zeroed at kernel start)
__device__ void stats_accum16(int stage, float* sAcc, const float* sum, const float* sq) {
  int lane = threadIdx.x & 31;
#pragma unroll
  for (int c = 0; c < 16; c++) {
    float v = sum[c];
#pragma unroll
    for (int o = 16; o > 0; o >>= 1) v += __shfl_xor_sync(0xffffffffu, v, o);
    float q = sq[c];
#pragma unroll
    for (int o = 16; o > 0; o >>= 1) q += __shfl_xor_sync(0xffffffffu, q, o);
    if (lane == 0) {
      atomicAdd(&sAcc[c], v);
      atomicAdd(&sAcc[16 + c], q);
    }
  }
  __syncthreads();
  if (threadIdx.x < 32) atomicAdd(&g_stats[stage][threadIdx.x], sAcc[threadIdx.x]);
}

// ---------------- K0: zero stats + build classifier table ----------------
__global__ void k_setup(const float* __restrict__ emb, const float* __restrict__ wc,
                        const float* __restrict__ bc) {
  int t = threadIdx.x;  // 512 threads
  if (t < 160) ((float*)g_stats)[t] = 0.f;
  int p = t >> 6, u = t & 63;
  float a = bc[u];
#pragma unroll
  for (int k = 0; k < 16; k++) a = fmaf(emb[p * 16 + k], wc[u * 32 + 16 + k], a);
  g_ctab[t] = a;
}

// ---------------- K1: stats of pos_values ----------------
__global__ void __launch_bounds__(256) k_stats0(const float2* __restrict__ x, int n) {
  __shared__ float sAcc[4];
  if (threadIdx.x < 4) sAcc[threadIdx.x] = 0.f;
  __syncthreads();
  float s0 = 0.f, s1 = 0.f, q0 = 0.f, q1 = 0.f;
  int stride = gridDim.x * blockDim.x;
  for (int i = blockIdx.x * blockDim.x + threadIdx.x; i < n; i += stride) {
    float2 v = x[i];
    s0 += v.x; s1 += v.y;
    q0 = fmaf(v.x, v.x, q0); q1 = fmaf(v.y, v.y, q1);
  }
#pragma unroll
  for (int o = 16; o > 0; o >>= 1) {
    s0 += __shfl_xor_sync(0xffffffffu, s0, o);
    s1 += __shfl_xor_sync(0xffffffffu, s1, o);
    q0 += __shfl_xor_sync(0xffffffffu, q0, o);
    q1 += __shfl_xor_sync(0xffffffffu, q1, o);
  }
  if ((threadIdx.x & 31) == 0) {
    atomicAdd(&sAcc[0], s0); atomicAdd(&sAcc[1], s1);
    atomicAdd(&sAcc[2], q0); atomicAdd(&sAcc[3], q1);
  }
  __syncthreads();
  if (threadIdx.x < 2) {
    atomicAdd(&g_stats[0][threadIdx.x], sAcc[threadIdx.x]);
    atomicAdd(&g_stats[0][16 + threadIdx.x], sAcc[2 + threadIdx.x]);
  }
}

// ---------------- K2: h1, stats1 ----------------
__global__ void __launch_bounds__(256) k_pass2(
    const float2* __restrict__ x, int n,
    const float* __restrict__ bn0g, const float* __restrict__ bn0b,
    const float* __restrict__ w1, const float* __restrict__ b1) {
  __shared__ float ss0[4];
  __shared__ float2 w1p[16], fb1p[8];
  __shared__ float sAcc[32];
  if (threadIdx.x < 32) sAcc[threadIdx.x] = 0.f;
  float invN = 1.0f / (float)n;
  fold_bn_layer1(invN, bn0g, bn0b, w1, b1, ss0, w1p, fb1p);
  __syncthreads();

  float sum[16], sq[16];
#pragma unroll
  for (int c = 0; c < 16; c++) { sum[c] = 0.f; sq[c] = 0.f; }
  int stride = gridDim.x * blockDim.x;
  for (int i = blockIdx.x * blockDim.x + threadIdx.x; i < n; i += stride) {
    float2 xv = x[i];
    float h[16];
    compute_h1(w1p, fb1p, xv.x, xv.y, h);
#pragma unroll
    for (int c = 0; c < 16; c++) { sum[c] += h[c]; sq[c] = fmaf(h[c], h[c], sq[c]); }
  }
  stats_accum16(1, sAcc, sum, sq);
}

// ---------------- K3: y1a = relu(L2(BN1 h1)), stats2 ----------------
__global__ void __launch_bounds__(256) k_pass3(
    const float2* __restrict__ x, int n,
    const float* __restrict__ bn0g, const float* __restrict__ bn0b,
    const float* __restrict__ bn1g, const float* __restrict__ bn1b,
    const float* __restrict__ w1, const float* __restrict__ b1,
    const float* __restrict__ w2, const float* __restrict__ b2) {
  __shared__ float ss0[4];  __shared__ float2 w1p[16], fb1p[8];
  __shared__ float ss1[32]; __shared__ float2 w2p[128], fb2p[8];
  __shared__ float sAcc[32];
  if (threadIdx.x < 32) sAcc[threadIdx.x] = 0.f;
  float invN = 1.0f / (float)n;
  fold_bn_layer1(invN, bn0g, bn0b, w1, b1, ss0, w1p, fb1p);
  fold_bn_layer16(1, invN, bn1g, bn1b, w2, b2, ss1, w2p, fb2p);
  __syncthreads();

  float sum[16], sq[16];
#pragma unroll
  for (int c = 0; c < 16; c++) { sum[c] = 0.f; sq[c] = 0.f; }
  int stride = gridDim.x * blockDim.x;
  for (int i = blockIdx.x * blockDim.x + threadIdx.x; i < n; i += 2 * stride) {
    int i1 = i + stride;
    float2 xa = x[i];
    float2 xb = (i1 < n) ? x[i1] : make_float2(0.f, 0.f);
    float h[2][16], y[2][16];
    compute_h1(w1p, fb1p, xa.x, xa.y, h[0]);
    compute_h1(w1p, fb1p, xb.x, xb.y, h[1]);
    layer16<2>(w2p, fb2p, h, y);
#pragma unroll
    for (int c = 0; c < 16; c++) { sum[c] += y[0][c]; sq[c] = fmaf(y[0][c], y[0][c], sq[c]); }
    if (i1 < n) {
#pragma unroll
      for (int c = 0; c < 16; c++) { sum[c] += y[1][c]; sq[c] = fmaf(y[1][c], y[1][c], sq[c]); }
    }
  }
  stats_accum16(2, sAcc, sum, sq);
}

// ---------------- K4: h2 = h1 + relu(L3(BN2 y1a)); store h2; stats3 ----------------
__global__ void __launch_bounds__(256) k_pass4(
    const float2* __restrict__ x, int n,
    const float* __restrict__ bn0g, const float* __restrict__ bn0b,
    const float* __restrict__ bn1g, const float* __restrict__ bn1b,
    const float* __restrict__ bn2g, const float* __restrict__ bn2b,
    const float* __restrict__ w1, const float* __restrict__ b1,
    const float* __restrict__ w2, const float* __restrict__ b2,
    const float* __restrict__ w3, const float* __restrict__ b3) {
  __shared__ float ss0[4];  __shared__ float2 w1p[16], fb1p[8];
  __shared__ float ss1[32]; __shared__ float2 w2p[128], fb2p[8];
  __shared__ float ss2[32]; __shared__ float2 w3p[128], fb3p[8];
  __shared__ float sAcc[32];
  if (threadIdx.x < 32) sAcc[threadIdx.x] = 0.f;
  float invN = 1.0f / (float)n;
  fold_bn_layer1(invN, bn0g, bn0b, w1, b1, ss0, w1p, fb1p);
  fold_bn_layer16(1, invN, bn1g, bn1b, w2, b2, ss1, w2p, fb2p);
  fold_bn_layer16(2, invN, bn2g, bn2b, w3, b3, ss2, w3p, fb3p);
  __syncthreads();

  float sum[16], sq[16];
#pragma unroll
  for (int c = 0; c < 16; c++) { sum[c] = 0.f; sq[c] = 0.f; }
  int stride = gridDim.x * blockDim.x;
  for (int i = blockIdx.x * blockDim.x + threadIdx.x; i < n; i += 2 * stride) {
    int i1 = i + stride;
    float2 xa = x[i];
    float2 xb = (i1 < n) ? x[i1] : make_float2(0.f, 0.f);
    float h[2][16], y[2][16], z[2][16];
    compute_h1(w1p, fb1p, xa.x, xa.y, h[0]);
    compute_h1(w1p, fb1p, xb.x, xb.y, h[1]);
    layer16<2>(w2p, fb2p, h, y);
    layer16<2>(w3p, fb3p, y, z);
#pragma unroll
    for (int r = 0; r < 2; r++)
#pragma unroll
      for (int c = 0; c < 16; c++) h[r][c] += z[r][c];   // h2
    // store + stats for row a
#pragma unroll
    for (int p = 0; p < 4; p++)
      g_h2[p * CAP + i] = make_float4(h[0][4 * p], h[0][4 * p + 1], h[0][4 * p + 2], h[0][4 * p + 3]);
#pragma unroll
    for (int c = 0; c < 16; c++) { sum[c] += h[0][c]; sq[c] = fmaf(h[0][c], h[0][c], sq[c]); }
    if (i1 < n) {
#pragma unroll
      for (int p = 0; p < 4; p++)
        g_h2[p * CAP + i1] = make_float4(h[1][4 * p], h[1][4 * p + 1], h[1][4 * p + 2], h[1][4 * p + 3]);
#pragma unroll
      for (int c = 0; c < 16; c++) { sum[c] += h[1][c]; sq[c] = fmaf(h[1][c], h[1][c], sq[c]); }
    }
  }
  stats_accum16(3, sAcc, sum, sq);
}

// ---------------- K5: y2a = relu(L4(BN3 h2)), stats4 ----------------
__global__ void __launch_bounds__(256) k_pass5(
    int n,
    const float* __restrict__ bn3g, const float* __restrict__ bn3b,
    const float* __restrict__ w4, const float* __restrict__ b4) {
  __shared__ float ss3[32]; __shared__ float2 w4p[128], fb4p[8];
  __shared__ float sAcc[32];
  if (threadIdx.x < 32) sAcc[threadIdx.x] = 0.f;
  float invN = 1.0f / (float)n;
  fold_bn_layer16(3, invN, bn3g, bn3b, w4, b4, ss3, w4p, fb4p);
  __syncthreads();

  float sum[16], sq[16];
#pragma unroll
  for (int c = 0; c < 16; c++) { sum[c] = 0.f; sq[c] = 0.f; }
  int stride = gridDim.x * blockDim.x;
  for (int i = blockIdx.x * blockDim.x + threadIdx.x; i < n; i += 2 * stride) {
    int i1 = i + stride;
    float h[2][16], y[2][16];
    load_h2(i, h[0]);
    if (i1 < n) load_h2(i1, h[1]);
    else {
#pragma unroll
      for (int c = 0; c < 16; c++) h[1][c] = 0.f;
    }
    layer16<2>(w4p, fb4p, h, y);
#pragma unroll
    for (int c = 0; c < 16; c++) { sum[c] += y[0][c]; sq[c] = fmaf(y[0][c], y[0][c], sq[c]); }
    if (i1 < n) {
#pragma unroll
      for (int c = 0; c < 16; c++) { sum[c] += y[1][c]; sq[c] = fmaf(y[1][c], y[1][c], sq[c]); }
    }
  }
  stats_accum16(4, sAcc, sum, sq);
}

// ---------------- K6: final — h3, classify, write out ----------------
__global__ void __launch_bounds__(256) k_final(
    int n, const int* __restrict__ idx, float* __restrict__ out,
    const float* __restrict__ bn3g, const float* __restrict__ bn3b,
    const float* __restrict__ bn4g, const float* __restrict__ bn4b,
    const float* __restrict__ w4, const float* __restrict__ b4,
    const float* __restrict__ w5, const float* __restrict__ b5,
    const float* __restrict__ wc) {
  __shared__ float ss3[32]; __shared__ float2 w4p[128], fb4p[8];
  __shared__ float ss4[32]; __shared__ float2 w5p[128], fb5p[8];
  __shared__ float2 wcp[512];     // wcp[k*32+p] = (wc[2p][k], wc[2p+1][k]) head
  __shared__ float2 sctab[256];   // ctab as pairs: [part*32 + p]
  float invN = 1.0f / (float)n;
  fold_bn_layer16(3, invN, bn3g, bn3b, w4, b4, ss3, w4p, fb4p);
  fold_bn_layer16(4, invN, bn4g, bn4b, w5, b5, ss4, w5p, fb5p);
  {
    int t = threadIdx.x;
#pragma unroll
    for (int e = t; e < 512; e += 256) {
      int k = e >> 5, p = e & 31;
      wcp[e] = make_float2(wc[(2 * p) * 32 + k], wc[(2 * p + 1) * 32 + k]);
    }
    sctab[t] = ((const float2*)g_ctab)[t];
  }
  __syncthreads();

  int i = blockIdx.x * blockDim.x + threadIdx.x;
  if (i >= n) return;

  float h[1][16], y[1][16], z[1][16];
  load_h2(i, h[0]);
  layer16<1>(w4p, fb4p, h, y);
  layer16<1>(w5p, fb5p, y, z);
  float h3[16];
#pragma unroll
  for (int c = 0; c < 16; c++) h3[c] = h[0][c] + z[0][c];

  int part = idx[i];
  const float2* cb = &sctab[part * 32];
  u64 acc[32];
#pragma unroll
  for (int p = 0; p < 32; p++) acc[p] = ldu64(&cb[p]);
#pragma unroll
  for (int k = 0; k < 16; k++) {
    u64 hk = pack2(h3[k], h3[k]);
#pragma unroll
    for (int p = 0; p < 32; p++) acc[p] = fma2(ldu64(&wcp[k * 32 + p]), hk, acc[p]);
  }
  float4* o = (float4*)(out + (size_t)i * 64);
#pragma unroll
  for (int q = 0; q < 16; q++) {
    float a, b, c, d;
    unpack2(acc[2 * q], a, b);
    unpack2(acc[2 * q + 1], c, d);
    o[q] = make_float4(a, b, c, d);
  }
}

// ---------------- launch ----------------
extern "C" void kernel_launch(void* const* d_in, const int* in_sizes, int n_in,
                              void* d_out, int out_size) {
  const float2* x  = (const float2*)d_in[0];
  const int* idx   = (const int*)d_in[1];
  const float* bn0g = (const float*)d_in[2],  *bn0b = (const float*)d_in[3];
  const float* bn1g = (const float*)d_in[4],  *bn1b = (const float*)d_in[5];
  const float* bn2g = (const float*)d_in[6],  *bn2b = (const float*)d_in[7];
  const float* bn3g = (const float*)d_in[8],  *bn3b = (const float*)d_in[9];
  const float* bn4g = (const float*)d_in[10], *bn4b = (const float*)d_in[11];
  const float* w1 = (const float*)d_in[12], *b1 = (const float*)d_in[13];
  const float* w2 = (const float*)d_in[14], *b2 = (const float*)d_in[15];
  const float* w3 = (const float*)d_in[16], *b3 = (const float*)d_in[17];
  const float* w4 = (const float*)d_in[18], *b4 = (const float*)d_in[19];
  const float* w5 = (const float*)d_in[20], *b5 = (const float*)d_in[21];
  const float* emb = (const float*)d_in[22];
  const float* wc  = (const float*)d_in[23], *bc = (const float*)d_in[24];
  float* out = (float*)d_out;
  int n = in_sizes[1];

  k_setup<<<1, 512>>>(emb, wc, bc);
  k_stats0<<<SGRID, 256>>>(x, n);
  k_pass2<<<SGRID, 256>>>(x, n, bn0g, bn0b, w1, b1);
  k_pass3<<<SGRID, 256>>>(x, n, bn0g, bn0b, bn1g, bn1b, w1, b1, w2, b2);
  k_pass4<<<SGRID, 256>>>(x, n, bn0g, bn0b, bn1g, bn1b, bn2g, bn2b, w1, b1, w2, b2, w3, b3);
  k_pass5<<<SGRID, 256>>>(n, bn3g, bn3b, w4, b4);
  k_final<<<(n + 255) / 256, 256>>>(n, idx, out, bn3g, bn3b, bn4g, bn4b, w4, b4, w5, b5, wc);
}

// round 8
// speedup vs baseline: 1.9200x; 1.9200x over previous
#include <cuda_runtime.h>

typedef unsigned long long u64;
typedef unsigned int u32;

#define CAP 2097152
#define EPSBN 1e-5f
#define SGRID 1184

__device__ float4 g_h2[4 * CAP];                    // h2 plane-major: [plane p][row]
__device__ float g_stats[5][32];                    // [stage][sum 0..15 | sumsq 0..15]
__device__ __align__(16) float g_ctab[8 * 64];      // emb@wc_tail^T + bc

// ---------------- packed f32x2 helpers ----------------
__device__ __forceinline__ u64 pack2(float x, float y) {
  u64 d;
  asm("mov.b64 %0, {%1, %2};" : "=l"(d) : "r"(__float_as_uint(x)), "r"(__float_as_uint(y)));
  return d;
}
__device__ __forceinline__ void unpack2(u64 a, float& x, float& y) {
  u32 lo, hi;
  asm("mov.b64 {%0, %1}, %2;" : "=r"(lo), "=r"(hi) : "l"(a));
  x = __uint_as_float(lo); y = __uint_as_float(hi);
}
__device__ __forceinline__ u64 fma2(u64 a, u64 b, u64 c) {
  u64 d;
  asm("fma.rn.f32x2 %0, %1, %2, %3;" : "=l"(d) : "l"(a), "l"(b), "l"(c));
  return d;
}
__device__ __forceinline__ u64 add2(u64 a, u64 b) {
  u64 d;
  asm("add.rn.f32x2 %0, %1, %2;" : "=l"(d) : "l"(a), "l"(b));
  return d;
}
__device__ __forceinline__ u64 ldu64(const float2* p) {
  return *reinterpret_cast<const u64*>(p);
}

// ---------------- BN folding into next linear ----------------
// y = W(x*sc + sh) + b  =>  W'[.,j] = W[.,j]*sc_j ; b' = b + W*sh
// wsp layout: wsp[j*8 + p] = (W'[2p][j], W'[2p+1][j])
__device__ void fold_bn_layer16(int stage, float invN,
                                const float* bng, const float* bnb,
                                const float* w, const float* bias,
                                float* ss, float2* wsp, float2* fbp) {
  int t = threadIdx.x;
  if (t < 16) {
    float m = g_stats[stage][t] * invN;
    float var = fmaf(-m, m, g_stats[stage][16 + t] * invN);
    float scale = rsqrtf(var + EPSBN) * bng[t];
    ss[t] = scale;
    ss[16 + t] = bnb[t] - m * scale;
  }
  __syncthreads();
  if (t < 128) {
    int j = t >> 3, p = t & 7;
    float s = ss[j];
    wsp[j * 8 + p] = make_float2(w[(2 * p) * 16 + j] * s, w[(2 * p + 1) * 16 + j] * s);
  }
  if (t < 8) {
    float a0 = bias[2 * t], a1 = bias[2 * t + 1];
#pragma unroll
    for (int j = 0; j < 16; j++) {
      float shj = ss[16 + j];
      a0 = fmaf(w[(2 * t) * 16 + j], shj, a0);
      a1 = fmaf(w[(2 * t + 1) * 16 + j], shj, a1);
    }
    fbp[t] = make_float2(a0, a1);
  }
}

__device__ void fold_bn_layer1(float invN,
                               const float* bng, const float* bnb,
                               const float* w1, const float* b1,
                               float* ss, float2* w1p, float2* fb1p) {
  int t = threadIdx.x;
  if (t < 2) {
    float m = g_stats[0][t] * invN;
    float var = fmaf(-m, m, g_stats[0][16 + t] * invN);
    float scale = rsqrtf(var + EPSBN) * bng[t];
    ss[t] = scale;
    ss[2 + t] = bnb[t] - m * scale;
  }
  __syncthreads();
  if (t < 16) {
    int j = t >> 3, p = t & 7;
    float s = ss[j];
    w1p[j * 8 + p] = make_float2(w1[(2 * p) * 2 + j] * s, w1[(2 * p + 1) * 2 + j] * s);
  }
  if (t < 8) {
    float a0 = fmaf(w1[(2 * t) * 2 + 0], ss[2], fmaf(w1[(2 * t) * 2 + 1], ss[3], b1[2 * t]));
    float a1 = fmaf(w1[(2 * t + 1) * 2 + 0], ss[2], fmaf(w1[(2 * t + 1) * 2 + 1], ss[3], b1[2 * t + 1]));
    fb1p[t] = make_float2(a0, a1);
  }
}

// ---------------- per-row layers (ALL arrays by reference => registers) ----------------
__device__ __forceinline__ void compute_h1(const float2* w1p, const float2* fb1p,
                                           float x0, float x1, float (&h)[16]) {
  u64 v0 = pack2(x0, x0), v1 = pack2(x1, x1);
#pragma unroll
  for (int p = 0; p < 8; p++) {
    u64 a = ldu64(&fb1p[p]);
    a = fma2(ldu64(&w1p[p]), v0, a);
    a = fma2(ldu64(&w1p[8 + p]), v1, a);
    float lo, hi; unpack2(a, lo, hi);
    h[2 * p] = fmaxf(lo, 0.f);
    h[2 * p + 1] = fmaxf(hi, 0.f);
  }
}

template <int R>
__device__ __forceinline__ void layer16R(const float2* wsp, const float2* fbp,
                                         const float (&v)[R][16], float (&o)[R][16]) {
  u64 acc[R][8];
#pragma unroll
  for (int p = 0; p < 8; p++) {
    u64 b = ldu64(&fbp[p]);
#pragma unroll
    for (int r = 0; r < R; r++) acc[r][p] = b;
  }
#pragma unroll
  for (int j = 0; j < 16; j++) {
    u64 w[8];
#pragma unroll
    for (int p = 0; p < 8; p++) w[p] = ldu64(&wsp[j * 8 + p]);
#pragma unroll
    for (int r = 0; r < R; r++) {
      u64 vr = pack2(v[r][j], v[r][j]);
#pragma unroll
      for (int p = 0; p < 8; p++) acc[r][p] = fma2(w[p], vr, acc[r][p]);
    }
  }
#pragma unroll
  for (int r = 0; r < R; r++)
#pragma unroll
    for (int p = 0; p < 8; p++) {
      float a, b; unpack2(acc[r][p], a, b);
      o[r][2 * p] = fmaxf(a, 0.f);
      o[r][2 * p + 1] = fmaxf(b, 0.f);
    }
}

__device__ __forceinline__ void load_h2(int row, float (&h)[16]) {
#pragma unroll
  for (int p = 0; p < 4; p++) {
    float4 f = g_h2[p * CAP + row];
    h[4 * p] = f.x; h[4 * p + 1] = f.y; h[4 * p + 2] = f.z; h[4 * p + 3] = f.w;
  }
}

// packed stats accumulation
__device__ __forceinline__ void stats_add(const float (&h)[16], u64 (&sum2)[8], u64 (&sq2)[8]) {
#pragma unroll
  for (int p = 0; p < 8; p++) {
    u64 hp = pack2(h[2 * p], h[2 * p + 1]);
    sum2[p] = add2(sum2[p], hp);
    sq2[p] = fma2(hp, hp, sq2[p]);
  }
}

__device__ void stats_flush(int stage, float* sAcc, u64 (&sum2)[8], u64 (&sq2)[8]) {
#pragma unroll
  for (int p = 0; p < 8; p++) {
#pragma unroll
    for (int o = 16; o > 0; o >>= 1) {
      sum2[p] = add2(sum2[p], __shfl_xor_sync(0xffffffffu, sum2[p], o));
      sq2[p] = add2(sq2[p], __shfl_xor_sync(0xffffffffu, sq2[p], o));
    }
    if ((threadIdx.x & 31) == 0) {
      float a, b;
      unpack2(sum2[p], a, b);
      atomicAdd(&sAcc[2 * p], a); atomicAdd(&sAcc[2 * p + 1], b);
      unpack2(sq2[p], a, b);
      atomicAdd(&sAcc[16 + 2 * p], a); atomicAdd(&sAcc[16 + 2 * p + 1], b);
    }
  }
  __syncthreads();
  if (threadIdx.x < 32) atomicAdd(&g_stats[stage][threadIdx.x], sAcc[threadIdx.x]);
}

// ---------------- K0: zero stats + classifier table ----------------
__global__ void k_setup(const float* __restrict__ emb, const float* __restrict__ wc,
                        const float* __restrict__ bc) {
  int t = threadIdx.x;  // 512
  if (t < 160) ((float*)g_stats)[t] = 0.f;
  int p = t >> 6, u = t & 63;
  float a = bc[u];
#pragma unroll
  for (int k = 0; k < 16; k++) a = fmaf(emb[p * 16 + k], wc[u * 32 + 16 + k], a);
  g_ctab[t] = a;
}

// ---------------- K1: stats of pos_values ----------------
__global__ void __launch_bounds__(256) k_stats0(const float2* __restrict__ x, int n) {
  __shared__ float sAcc[4];
  if (threadIdx.x < 4) sAcc[threadIdx.x] = 0.f;
  __syncthreads();
  float s0 = 0.f, s1 = 0.f, q0 = 0.f, q1 = 0.f;
  int stride = gridDim.x * blockDim.x;
  for (int i = blockIdx.x * blockDim.x + threadIdx.x; i < n; i += stride) {
    float2 v = x[i];
    s0 += v.x; s1 += v.y;
    q0 = fmaf(v.x, v.x, q0); q1 = fmaf(v.y, v.y, q1);
  }
#pragma unroll
  for (int o = 16; o > 0; o >>= 1) {
    s0 += __shfl_xor_sync(0xffffffffu, s0, o);
    s1 += __shfl_xor_sync(0xffffffffu, s1, o);
    q0 += __shfl_xor_sync(0xffffffffu, q0, o);
    q1 += __shfl_xor_sync(0xffffffffu, q1, o);
  }
  if ((threadIdx.x & 31) == 0) {
    atomicAdd(&sAcc[0], s0); atomicAdd(&sAcc[1], s1);
    atomicAdd(&sAcc[2], q0); atomicAdd(&sAcc[3], q1);
  }
  __syncthreads();
  if (threadIdx.x < 2) {
    atomicAdd(&g_stats[0][threadIdx.x], sAcc[threadIdx.x]);
    atomicAdd(&g_stats[0][16 + threadIdx.x], sAcc[2 + threadIdx.x]);
  }
}

// ---------------- K2: h1, stats1 ----------------
__global__ void __launch_bounds__(256) k_pass2(
    const float2* __restrict__ x, int n,
    const float* __restrict__ bn0g, const float* __restrict__ bn0b,
    const float* __restrict__ w1, const float* __restrict__ b1) {
  __shared__ float ss0[4];
  __shared__ float2 w1p[16], fb1p[8];
  __shared__ float sAcc[32];
  if (threadIdx.x < 32) sAcc[threadIdx.x] = 0.f;
  float invN = 1.0f / (float)n;
  fold_bn_layer1(invN, bn0g, bn0b, w1, b1, ss0, w1p, fb1p);
  __syncthreads();

  u64 sum2[8], sq2[8];
#pragma unroll
  for (int p = 0; p < 8; p++) { sum2[p] = 0ull; sq2[p] = 0ull; }
  int stride = gridDim.x * blockDim.x;
  for (int i = blockIdx.x * blockDim.x + threadIdx.x; i < n; i += stride) {
    float2 xv = x[i];
    float h[16];
    compute_h1(w1p, fb1p, xv.x, xv.y, h);
    stats_add(h, sum2, sq2);
  }
  stats_flush(1, sAcc, sum2, sq2);
}

// ---------------- K3: y1a, stats2 ----------------
__global__ void __launch_bounds__(256) k_pass3(
    const float2* __restrict__ x, int n,
    const float* __restrict__ bn0g, const float* __restrict__ bn0b,
    const float* __restrict__ bn1g, const float* __restrict__ bn1b,
    const float* __restrict__ w1, const float* __restrict__ b1,
    const float* __restrict__ w2, const float* __restrict__ b2) {
  __shared__ float ss0[4];  __shared__ float2 w1p[16], fb1p[8];
  __shared__ float ss1[32]; __shared__ float2 w2p[128], fb2p[8];
  __shared__ float sAcc[32];
  if (threadIdx.x < 32) sAcc[threadIdx.x] = 0.f;
  float invN = 1.0f / (float)n;
  fold_bn_layer1(invN, bn0g, bn0b, w1, b1, ss0, w1p, fb1p);
  fold_bn_layer16(1, invN, bn1g, bn1b, w2, b2, ss1, w2p, fb2p);
  __syncthreads();

  u64 sum2[8], sq2[8];
#pragma unroll
  for (int p = 0; p < 8; p++) { sum2[p] = 0ull; sq2[p] = 0ull; }
  int stride = gridDim.x * blockDim.x;
  for (int i = blockIdx.x * blockDim.x + threadIdx.x; i < n; i += 2 * stride) {
    int i1 = i + stride;
    float2 xa = x[i];
    float2 xb = (i1 < n) ? x[i1] : make_float2(0.f, 0.f);
    float h[2][16], y[2][16];
    compute_h1(w1p, fb1p, xa.x, xa.y, h[0]);
    compute_h1(w1p, fb1p, xb.x, xb.y, h[1]);
    layer16R<2>(w2p, fb2p, h, y);
    stats_add(y[0], sum2, sq2);
    if (i1 < n) stats_add(y[1], sum2, sq2);
  }
  stats_flush(2, sAcc, sum2, sq2);
}

// ---------------- K4: h2 = h1 + L3(BN2 y1a); store; stats3 ----------------
__global__ void __launch_bounds__(256) k_pass4(
    const float2* __restrict__ x, int n,
    const float* __restrict__ bn0g, const float* __restrict__ bn0b,
    const float* __restrict__ bn1g, const float* __restrict__ bn1b,
    const float* __restrict__ bn2g, const float* __restrict__ bn2b,
    const float* __restrict__ w1, const float* __restrict__ b1,
    const float* __restrict__ w2, const float* __restrict__ b2,
    const float* __restrict__ w3, const float* __restrict__ b3) {
  __shared__ float ss0[4];  __shared__ float2 w1p[16], fb1p[8];
  __shared__ float ss1[32]; __shared__ float2 w2p[128], fb2p[8];
  __shared__ float ss2[32]; __shared__ float2 w3p[128], fb3p[8];
  __shared__ float sAcc[32];
  if (threadIdx.x < 32) sAcc[threadIdx.x] = 0.f;
  float invN = 1.0f / (float)n;
  fold_bn_layer1(invN, bn0g, bn0b, w1, b1, ss0, w1p, fb1p);
  fold_bn_layer16(1, invN, bn1g, bn1b, w2, b2, ss1, w2p, fb2p);
  fold_bn_layer16(2, invN, bn2g, bn2b, w3, b3, ss2, w3p, fb3p);
  __syncthreads();

  u64 sum2[8], sq2[8];
#pragma unroll
  for (int p = 0; p < 8; p++) { sum2[p] = 0ull; sq2[p] = 0ull; }
  int stride = gridDim.x * blockDim.x;
  for (int i = blockIdx.x * blockDim.x + threadIdx.x; i < n; i += 2 * stride) {
    int i1 = i + stride;
    float2 xa = x[i];
    float2 xb = (i1 < n) ? x[i1] : make_float2(0.f, 0.f);
    float h[2][16], y[2][16], z[2][16];
    compute_h1(w1p, fb1p, xa.x, xa.y, h[0]);
    compute_h1(w1p, fb1p, xb.x, xb.y, h[1]);
    layer16R<2>(w2p, fb2p, h, y);
    layer16R<2>(w3p, fb3p, y, z);
#pragma unroll
    for (int r = 0; r < 2; r++)
#pragma unroll
      for (int c = 0; c < 16; c++) h[r][c] += z[r][c];   // h2
#pragma unroll
    for (int p = 0; p < 4; p++)
      g_h2[p * CAP + i] = make_float4(h[0][4 * p], h[0][4 * p + 1], h[0][4 * p + 2], h[0][4 * p + 3]);
    stats_add(h[0], sum2, sq2);
    if (i1 < n) {
#pragma unroll
      for (int p = 0; p < 4; p++)
        g_h2[p * CAP + i1] = make_float4(h[1][4 * p], h[1][4 * p + 1], h[1][4 * p + 2], h[1][4 * p + 3]);
      stats_add(h[1], sum2, sq2);
    }
  }
  stats_flush(3, sAcc, sum2, sq2);
}

// ---------------- K5: y2a, stats4 ----------------
__global__ void __launch_bounds__(256) k_pass5(
    int n,
    const float* __restrict__ bn3g, const float* __restrict__ bn3b,
    const float* __restrict__ w4, const float* __restrict__ b4) {
  __shared__ float ss3[32]; __shared__ float2 w4p[128], fb4p[8];
  __shared__ float sAcc[32];
  if (threadIdx.x < 32) sAcc[threadIdx.x] = 0.f;
  float invN = 1.0f / (float)n;
  fold_bn_layer16(3, invN, bn3g, bn3b, w4, b4, ss3, w4p, fb4p);
  __syncthreads();

  u64 sum2[8], sq2[8];
#pragma unroll
  for (int p = 0; p < 8; p++) { sum2[p] = 0ull; sq2[p] = 0ull; }
  int stride = gridDim.x * blockDim.x;
  for (int i = blockIdx.x * blockDim.x + threadIdx.x; i < n; i += 2 * stride) {
    int i1 = i + stride;
    float h[2][16], y[2][16];
    load_h2(i, h[0]);
    if (i1 < n) load_h2(i1, h[1]);
    else {
#pragma unroll
      for (int c = 0; c < 16; c++) h[1][c] = 0.f;
    }
    layer16R<2>(w4p, fb4p, h, y);
    stats_add(y[0], sum2, sq2);
    if (i1 < n) stats_add(y[1], sum2, sq2);
  }
  stats_flush(4, sAcc, sum2, sq2);
}

// ---------------- K6: final — h3, classify, coalesced write ----------------
__global__ void __launch_bounds__(256) k_final(
    int n, const int* __restrict__ idx, float* __restrict__ out,
    const float* __restrict__ bn3g, const float* __restrict__ bn3b,
    const float* __restrict__ bn4g, const float* __restrict__ bn4b,
    const float* __restrict__ w4, const float* __restrict__ b4,
    const float* __restrict__ w5, const float* __restrict__ b5,
    const float* __restrict__ wc) {
  __shared__ float ss3[32]; __shared__ float2 w4p[128], fb4p[8];
  __shared__ float ss4[32]; __shared__ float2 w5p[128], fb5p[8];
  __shared__ float2 wcp[512];          // wcp[k*32+p] = (wc[2p][k], wc[2p+1][k]) head
  __shared__ float2 sctab[256];        // ctab pairs: [part*32 + p]
  __shared__ float2 so2[16 * 257];     // staging: [pair p][row], padded stride 257
  float invN = 1.0f / (float)n;
  fold_bn_layer16(3, invN, bn3g, bn3b, w4, b4, ss3, w4p, fb4p);
  fold_bn_layer16(4, invN, bn4g, bn4b, w5, b5, ss4, w5p, fb5p);
  int t = threadIdx.x;
  {
#pragma unroll
    for (int e = t; e < 512; e += 256) {
      int k = e >> 5, p = e & 31;
      wcp[e] = make_float2(wc[(2 * p) * 32 + k], wc[(2 * p + 1) * 32 + k]);
    }
    sctab[t] = ((const float2*)g_ctab)[t];
  }
  __syncthreads();

  int blockBase = blockIdx.x * 256;
  int i = blockBase + t;
  bool valid = (i < n);

  float h3[16];
  int part = 0;
  if (valid) {
    float h[1][16], y[1][16], z[1][16];
    load_h2(i, h[0]);
    layer16R<1>(w4p, fb4p, h, y);
    layer16R<1>(w5p, fb5p, y, z);
#pragma unroll
    for (int c = 0; c < 16; c++) h3[c] = h[0][c] + z[0][c];
    part = idx[i];
  } else {
#pragma unroll
    for (int c = 0; c < 16; c++) h3[c] = 0.f;
  }

  float2* o2 = (float2*)out;
#pragma unroll
  for (int half = 0; half < 2; half++) {
    u64 acc[16];
#pragma unroll
    for (int p = 0; p < 16; p++) acc[p] = ldu64(&sctab[part * 32 + half * 16 + p]);
#pragma unroll
    for (int k = 0; k < 16; k++) {
      u64 hk = pack2(h3[k], h3[k]);
#pragma unroll
      for (int p = 0; p < 16; p++)
        acc[p] = fma2(ldu64(&wcp[k * 32 + half * 16 + p]), hk, acc[p]);
    }
    // stage
#pragma unroll
    for (int p = 0; p < 16; p++)
      *reinterpret_cast<u64*>(&so2[p * 257 + t]) = acc[p];
    __syncthreads();
    // coalesced write: 16 pairs per row, 4096 float2 per block-half
#pragma unroll
    for (int q = 0; q < 16; q++) {
      int li = q * 256 + t;
      int r = li >> 4, p = li & 15;
      int row = blockBase + r;
      if (row < n) o2[(size_t)row * 32 + half * 16 + p] = so2[p * 257 + r];
    }
    __syncthreads();
  }
}

// ---------------- launch ----------------
extern "C" void kernel_launch(void* const* d_in, const int* in_sizes, int n_in,
                              void* d_out, int out_size) {
  const float2* x  = (const float2*)d_in[0];
  const int* idx   = (const int*)d_in[1];
  const float* bn0g = (const float*)d_in[2],  *bn0b = (const float*)d_in[3];
  const float* bn1g = (const float*)d_in[4],  *bn1b = (const float*)d_in[5];
  const float* bn2g = (const float*)d_in[6],  *bn2b = (const float*)d_in[7];
  const float* bn3g = (const float*)d_in[8],  *bn3b = (const float*)d_in[9];
  const float* bn4g = (const float*)d_in[10], *bn4b = (const float*)d_in[11];
  const float* w1 = (const float*)d_in[12], *b1 = (const float*)d_in[13];
  const float* w2 = (const float*)d_in[14], *b2 = (const float*)d_in[15];
  const float* w3 = (const float*)d_in[16], *b3 = (const float*)d_in[17];
  const float* w4 = (const float*)d_in[18], *b4 = (const float*)d_in[19];
  const float* w5 = (const float*)d_in[20], *b5 = (const float*)d_in[21];
  const float* emb = (const float*)d_in[22];
  const float* wc  = (const float*)d_in[23], *bc = (const float*)d_in[24];
  float* out = (float*)d_out;
  int n = in_sizes[1];

  k_setup<<<1, 512>>>(emb, wc, bc);
  k_stats0<<<SGRID, 256>>>(x, n);
  k_pass2<<<SGRID, 256>>>(x, n, bn0g, bn0b, w1, b1);
  k_pass3<<<SGRID, 256>>>(x, n, bn0g, bn0b, bn1g, bn1b, w1, b1, w2, b2);
  k_pass4<<<SGRID, 256>>>(x, n, bn0g, bn0b, bn1g, bn1b, bn2g, bn2b, w1, b1, w2, b2, w3, b3);
  k_pass5<<<SGRID, 256>>>(n, bn3g, bn3b, w4, b4);
  k_final<<<(n + 255) / 256, 256>>>(n, idx, out, bn3g, bn3b, bn4g, bn4b, w4, b4, w5, b5, wc);
}